// round 5
// baseline (speedup 1.0000x reference)
#include <cuda_runtime.h>
#include <cstdint>
#include <math.h>

#define NB 4
#define LQ 128
#define DIM 128
#define HID 512
#define WWIN 5
#define MAXSEG 44
#define MAXINT 384
#define OW (2 + 2*LQ*DIM)   // 32770 floats per batch row

#define CL 8                // cluster size (CTAs per batch chain)
#define TPB2 256
#define W1P 132             // padded row strides (528B, 16B-multiple)
#define W3P 516             // 2064B, 16B-multiple

// ---------------- device scratch (no allocations allowed) ----------------
static __device__ float g_enc[NB*LQ*DIM];
static __device__ int   g_nInt[NB];
static __device__ float g_dt[NB*MAXINT];
static __device__ int   g_envSeg[NB*MAXINT];
static __device__ int   g_gsel[NB*LQ];
static __device__ int   g_segS[NB*MAXSEG];
static __device__ int   g_segE[NB*MAXSEG];

__device__ __forceinline__ float softplusf(float x){
    return fmaxf(x, 0.f) + log1pf(expf(-fabsf(x)));
}

__device__ __forceinline__ bool is_index_arr(const void* p){
    int v = ((const int*)p)[0];
    return (v >= 0 && v < 1000000);
}

__device__ __forceinline__ uint32_t smem_u32(const void* p){
    return (uint32_t)__cvta_generic_to_shared(p);
}
__device__ __forceinline__ uint32_t mapa_u32(uint32_t la, uint32_t rank){
    uint32_t ra;
    asm volatile("mapa.shared::cluster.u32 %0, %1, %2;" : "=r"(ra) : "r"(la), "r"(rank));
    return ra;
}
// remote smem store with mbarrier transaction completion
__device__ __forceinline__ void st_async_f(uint32_t raddr, uint32_t rmbar, float v){
    asm volatile("st.async.shared::cluster.mbarrier::complete_tx::bytes.b32 [%0], %1, [%2];"
                 :: "r"(raddr), "r"(__float_as_uint(v)), "r"(rmbar) : "memory");
}
__device__ __forceinline__ void mbar_init(uint32_t mbar, uint32_t cnt){
    asm volatile("mbarrier.init.shared.b64 [%0], %1;" :: "r"(mbar), "r"(cnt) : "memory");
}
__device__ __forceinline__ void mbar_inval(uint32_t mbar){
    asm volatile("mbarrier.inval.shared.b64 [%0];" :: "r"(mbar) : "memory");
}
__device__ __forceinline__ void mbar_expect(uint32_t mbar, uint32_t bytes){
    asm volatile("mbarrier.arrive.expect_tx.shared.b64 _, [%0], %1;"
                 :: "r"(mbar), "r"(bytes) : "memory");
}
__device__ __forceinline__ void mbar_wait(uint32_t mbar, uint32_t parity){
    asm volatile("{\n\t"
        ".reg .pred P;\n\t"
        "LW%=:\n\t"
        "mbarrier.try_wait.parity.acquire.cluster.shared::cta.b64 P, [%0], %1, 0x989680;\n\t"
        "@P bra LD%=;\n\t"
        "bra LW%=;\n\t"
        "LD%=:\n\t"
        "}" :: "r"(mbar), "r"(parity) : "memory");
}

#define CLUSTER_SYNC_() do { \
    asm volatile("barrier.cluster.arrive.aligned;" ::: "memory"); \
    asm volatile("barrier.cluster.wait.aligned;" ::: "memory"); } while(0)

// ---------------- kernel 1: encoder (also writes traj_t) ----------------
__global__ void enc_k(const int* __restrict__ hi, const float* __restrict__ emb,
                      const float* __restrict__ w1, const float* __restrict__ b1,
                      const float* __restrict__ w2, const float* __restrict__ b2,
                      float* __restrict__ out)
{
    int l = blockIdx.x, b = blockIdx.y, t = threadIdx.x;
    __shared__ float e[DIM], h[DIM];
    int idx = hi[b*LQ + l];
    e[t] = emb[(size_t)idx*DIM + t];
    __syncthreads();
    float a = b1[t];
#pragma unroll 8
    for (int k = 0; k < DIM; k++) a = fmaf(e[k], w1[k*DIM + t], a);
    h[t] = fmaxf(a, 0.f);
    __syncthreads();
    float a2 = b2[t];
#pragma unroll 8
    for (int k = 0; k < DIM; k++) a2 = fmaf(h[k], w2[k*DIM + t], a2);
    g_enc[(b*LQ + l)*DIM + t] = a2;
    out[(size_t)b*OW + 2 + LQ*DIM + l*DIM + t] = a2;   // traj_t
}

// ---------------- block reduction over 128 threads ----------------
__device__ __forceinline__ float blkRed(float v, int op, float* sb){
#pragma unroll
    for (int o = 16; o > 0; o >>= 1){
        float v2 = __shfl_xor_sync(0xffffffffu, v, o);
        v = op ? fmaxf(v, v2) : (v + v2);
    }
    int w = threadIdx.x >> 5;
    if ((threadIdx.x & 31) == 0) sb[w] = v;
    __syncthreads();
    float r = op ? fmaxf(fmaxf(sb[0], sb[1]), fmaxf(sb[2], sb[3]))
                 : ((sb[0] + sb[1]) + (sb[2] + sb[3]));
    __syncthreads();
    return r;
}

// ---------------- kernel 2: APT partition + time-grid planning ----------------
__global__ void plan_k(const float* __restrict__ ht, const int* __restrict__ hl,
                       const void* __restrict__ p16, const void* __restrict__ p17,
                       const void* __restrict__ p18)
{
    int b = blockIdx.x, t = threadIdx.x;
    const float* pt;
    if (is_index_arr(p16)) pt = (const float*)p18;   // order: pos,neg,pt
    else                   pt = (const float*)p16;   // order: pt,pos,neg

    __shared__ double times[LQ];
    __shared__ double bounds[MAXSEG + 2];
    __shared__ int starts[MAXSEG + 1];
    __shared__ float sb[4];
    __shared__ int sj, snb, sns, sm_m, scum;
    __shared__ double ts[LQ + 8];

    int n = hl[b]; if (n > LQ) n = LQ;
    if (t < n) times[t] = (double)ht[b*LQ + t];
    if (t == 0){ sj = 0; snb = 1; sns = 1; bounds[0] = (double)ht[b*LQ]; starts[0] = 0; scum = 0; }
    __syncthreads();

    if (n >= 2*WWIN){
        for (;;){
            __syncthreads();
            int j = sj;
            if (j > n - 2*WWIN) break;
            float sL = 0.f, sR = 0.f;
            const float* base = &g_enc[(b*LQ + j)*DIM + t];
#pragma unroll
            for (int r = 0; r < WWIN; r++){ sL += base[r*DIM]; sR += base[(WWIN + r)*DIM]; }
            sL /= (float)WWIN; sR /= (float)WWIN;
            float mL = blkRed(sL, 1, sb);
            float mR = blkRed(sR, 1, sb);
            float eL = expf(sL - mL), eR = expf(sR - mR);
            float suL = blkRed(eL, 0, sb);
            float suR = blkRed(eR, 0, sb);
            float p = eL/suL + 1e-8f;
            float q = eR/suR + 1e-8f;
            float ps = blkRed(p, 0, sb);
            float qs = blkRed(q, 0, sb);
            p /= ps; q /= qs;
            float m  = 0.5f*(p + q);
            float c  = 0.5f*p*logf(p/m) + 0.5f*q*logf(q/m);
            float jsd = blkRed(c, 0, sb);
            if (t == 0){
                if (jsd > 0.5f){
                    bounds[snb] = 0.5*(times[j + WWIN - 1] + times[j + WWIN]);
                    snb++;
                    starts[sns] = j + WWIN; sns++;
                    sj = j + WWIN;
                } else sj = j + 1;
            }
        }
    }
    __syncthreads();
    if (t == 0){
        if (times[n-1] > bounds[snb-1]) { bounds[snb] = times[n-1]; snb++; }
    }
    __syncthreads();

    int nseg = sns, nb2 = snb;
    for (int si = 0; si < nseg; si++){
        int s = starts[si];
        int e = (si + 1 < nseg) ? starts[si+1] - 1 : n - 1;
        if (t == 0){
            g_segS[b*MAXSEG + si] = s; g_segE[b*MAXSEG + si] = e;
            double t0 = bounds[si];
            double t1 = (si + 1 < nb2) ? bounds[si+1] : bounds[nb2-1];
            int m = 0; ts[m++] = t0;
            for (int i = s; i <= e; i++){
                double d = times[i];
                if (d >= t0 && d <= t1 && d != ts[m-1]) ts[m++] = d;
            }
            if (t1 != ts[m-1]) ts[m++] = t1;
            for (int k = 1; k < m; k++)
                if (ts[k] - ts[k-1] < 1e-6) ts[k] = ts[k-1] + 1e-6;
            for (int k = 0; k < m - 1; k++){
                g_dt[b*MAXINT + scum + k] = (float)(ts[k+1] - ts[k]);
                g_envSeg[b*MAXINT + scum + k] = si;
            }
            sm_m = m;
        }
        __syncthreads();
        int m = sm_m, cum = scum;
        for (int i = s + t; i <= e; i += blockDim.x){
            double ti = times[i];
            int best = 0; double bd = fabs(ts[0] - ti);
            for (int k = 1; k < m; k++){
                double dd = fabs(ts[k] - ti);
                if (dd < bd){ bd = dd; best = k; }
            }
            g_gsel[b*LQ + i] = cum + best;
        }
        __syncthreads();
        if (t == 0) scum += m - 1;
        __syncthreads();
    }
    if (t == 0){
        int cum = scum;
        double lb = bounds[nb2-1];
        double ptb = (double)pt[b];
        if (ptb > lb + 1e-6){
            double t1 = ptb;
            if (t1 - lb < 1e-6) t1 = lb + 1e-6;
            g_dt[b*MAXINT + cum] = (float)(t1 - lb);
            g_envSeg[b*MAXINT + cum] = nseg - 1;
            cum++;
        }
        g_nInt[b] = cum;
    }
}

// ---------------- kernel 3: clustered Euler ODE (async protocol) ----------------
// NOTE: header padded to 32 bytes so every float array below sits at a
// 16-byte-aligned offset (all array sizes and strides are 16B multiples);
// float4 LDS requires it.
struct __align__(16) OdeSmem {
    unsigned long long mb[4];   // 0: h1, 1: h2, 2: z, 3: pad (32B header)
    float w1t[64*W1P];          // layer1 z-half slice, transposed [o][k]
    float w3t[16*W3P];          // layer3 slice transposed
    float wenv[128*64];         // env-half of W1 slice (precompute only)
    float envs[MAXSEG*DIM];     // per-segment env
    float cenvAll[MAXSEG*64];   // per-segment folded layer1 constant
    float z[DIM];
    float h1[HID];
    float h2[HID];
    float b2s[64];
    float b3s[16];
    float part[4*64];           // reduction scratch (also 16x16 for L3)
    float dtv[MAXINT];
    int   eseg[MAXINT];
    int   segS[MAXSEG];
    int   segE[MAXSEG];
    int   gsel[LQ];
    float red[8];
};

extern __shared__ __align__(16) char ode_raw[];

__global__ void __launch_bounds__(TPB2, 1) __cluster_dims__(CL, 1, 1)
ode_cl_k(const float* __restrict__ usert, const int* __restrict__ u,
         const float* __restrict__ vw1, const float* __restrict__ vb1,
         const float* __restrict__ vw2, const float* __restrict__ vb2,
         const float* __restrict__ vw3, const float* __restrict__ vb3,
         const float* __restrict__ emb, const int* __restrict__ hl,
         const void* __restrict__ p16, const void* __restrict__ p17,
         const void* __restrict__ p18,
         float* __restrict__ out)
{
    OdeSmem* S = (OdeSmem*)ode_raw;
    int t = threadIdx.x;
    uint32_t cr; asm("mov.u32 %0, %%cluster_ctarank;" : "=r"(cr));
    int b = blockIdx.x / CL;

    const int *pos, *neg;
    if (is_index_arr(p16)) { pos = (const int*)p16; neg = (const int*)p17; }
    else                   { pos = (const int*)p17; neg = (const int*)p18; }

    const int o64 = t & 63, p4 = t >> 6;     // layer1/2 mapping
    const int o16 = t & 15, p16i = t >> 4;   // layer3 mapping

    // ---- layer-2 weight slice into REGISTERS ----
    float w2r[128];
    {
        const float* base = &vw2[(size_t)(p4*128)*HID + cr*64 + o64];
#pragma unroll
        for (int kk = 0; kk < 128; kk++) w2r[kk] = base[(size_t)kk*HID];
    }

    // ---- smem weights (layer1 z-half, layer3) ----
    for (int idx = t; idx < 64*128; idx += TPB2){
        int k = idx >> 6, o = idx & 63;
        S->w1t[o*W1P + k] = vw1[k*HID + cr*64 + o];
    }
    for (int idx = t; idx < 16*512; idx += TPB2){
        int k = idx >> 4, o = idx & 15;
        S->w3t[o*W3P + k] = vw3[k*DIM + cr*16 + o];
    }
    // env-half of W1 (staged once for cenv precompute)
    for (int idx = t; idx < 128*64; idx += TPB2){
        int k = idx >> 6, o = idx & 63;
        S->wenv[k*64 + o] = vw1[(DIM + k)*HID + cr*64 + o];
    }
    if (t < 64) S->b2s[t] = vb2[cr*64 + t];
    if (t < 16) S->b3s[t] = vb3[cr*16 + t];
    for (int i = t; i < MAXINT; i += TPB2){
        S->dtv[i] = g_dt[b*MAXINT + i];
        S->eseg[i] = g_envSeg[b*MAXINT + i];
    }
    for (int i = t; i < MAXSEG; i += TPB2){
        S->segS[i] = g_segS[b*MAXSEG + i];
        S->segE[i] = g_segE[b*MAXSEG + i];
    }
    for (int i = t; i < LQ; i += TPB2) S->gsel[i] = g_gsel[b*LQ + i];
    if (t < DIM) S->z[t] = usert[(size_t)u[b]*DIM + t];

    uint32_t mb_h1 = smem_u32(&S->mb[0]);
    uint32_t mb_h2 = smem_u32(&S->mb[1]);
    uint32_t mb_z  = smem_u32(&S->mb[2]);
    if (t == 0){ mbar_init(mb_h1, 1); mbar_init(mb_h2, 1); mbar_init(mb_z, 1); }
    __syncthreads();

    int nInt = g_nInt[b];
    int nseg = S->eseg[nInt - 1] + 1;
    int n = hl[b]; if (n > LQ) n = LQ;

    // ---- precompute per-segment env & cenv ----
    for (int si = 0; si < nseg; si++){
        int s = S->segS[si], e = S->segE[si];
        if (t < DIM){
            float a = 0.f;
            for (int r2 = s; r2 <= e; r2++) a += g_enc[(b*LQ + r2)*DIM + t];
            S->envs[si*DIM + t] = a / (float)(e - s + 1);
        }
    }
    __syncthreads();
    for (int si = 0; si < nseg; si++){
        float a = 0.f;
        const float* ep = &S->envs[si*DIM + p4*32];
        const float* wp = &S->wenv[(p4*32)*64 + o64];
#pragma unroll 8
        for (int kk = 0; kk < 32; kk++) a = fmaf(ep[kk], wp[kk*64], a);
        S->part[p4*64 + o64] = a;
        __syncthreads();
        if (t < 64)
            S->cenvAll[si*64 + t] = vb1[cr*64 + t] +
                ((S->part[t] + S->part[64 + t]) + (S->part[128 + t] + S->part[192 + t]));
        __syncthreads();
    }

    // ---- post expects for substep 0, then cluster-wide go ----
    if (t == 0){
        mbar_expect(mb_h1, 2048);
        mbar_expect(mb_h2, 2048);
        mbar_expect(mb_z,  512);
    }
    __syncthreads();
    CLUSTER_SYNC_();

    // local addresses of this CTA's produced slices (same offset in every CTA)
    uint32_t la_h1 = smem_u32(&S->h1[cr*64 + o64]);
    uint32_t la_h2 = smem_u32(&S->h2[cr*64 + o64]);
    uint32_t la_z  = smem_u32(&S->z [cr*16 + o16]);

    // initial (grid 0) state writes
    {
        int o = t & 15, ib = t >> 4;
#pragma unroll
        for (int pass = 0; pass < 8; pass++){
            int i = pass*16 + ib;
            if (i < n && S->gsel[i] == 0)
                out[(size_t)b*OW + 2 + i*DIM + cr*16 + o] = S->z[cr*16 + o];
        }
    }

    int ph = 0;   // substep counter (parity)
    for (int j = 0; j < nInt; j++){
        const float* cenv = &S->cenvAll[S->eseg[j]*64];
        float dtsub = 0.5f * S->dtv[j];   // dt / NSUB, NSUB=2
        for (int sub = 0; sub < 2; sub++){
            uint32_t par = (uint32_t)(ph & 1);
            // ---------- layer 1: 64 out x 128 k ----------
            {
                const float* wr = &S->w1t[o64*W1P + p4*32];
                const float* zr = &S->z[p4*32];
                float4 a4 = make_float4(0.f,0.f,0.f,0.f);
#pragma unroll
                for (int kk = 0; kk < 8; kk++){
                    float4 w = *(const float4*)(wr + kk*4);
                    float4 x = *(const float4*)(zr + kk*4);
                    a4.x = fmaf(w.x, x.x, a4.x); a4.y = fmaf(w.y, x.y, a4.y);
                    a4.z = fmaf(w.z, x.z, a4.z); a4.w = fmaf(w.w, x.w, a4.w);
                }
                S->part[p4*64 + o64] = (a4.x + a4.y) + (a4.z + a4.w);
            }
            __syncthreads();
            if (t < 64){
                float v = cenv[t] +
                    ((S->part[t] + S->part[64 + t]) + (S->part[128 + t] + S->part[192 + t]));
                float hv = softplusf(v);
#pragma unroll
                for (int d = 0; d < CL; d++)
                    st_async_f(mapa_u32(la_h1, d), mapa_u32(mb_h1, d), hv);
            }
            mbar_wait(mb_h1, par);
            // ---------- layer 2: 64 out x 512 k (weights in registers) ----------
            {
                const float4* hr = (const float4*)&S->h1[p4*128];
                float4 a4 = make_float4(0.f,0.f,0.f,0.f);
#pragma unroll
                for (int kk = 0; kk < 32; kk++){
                    float4 h = hr[kk];
                    a4.x = fmaf(h.x, w2r[kk*4+0], a4.x);
                    a4.y = fmaf(h.y, w2r[kk*4+1], a4.y);
                    a4.z = fmaf(h.z, w2r[kk*4+2], a4.z);
                    a4.w = fmaf(h.w, w2r[kk*4+3], a4.w);
                }
                S->part[p4*64 + o64] = (a4.x + a4.y) + (a4.z + a4.w);
            }
            __syncthreads();
            if (t < 64){
                float v = S->b2s[t] +
                    ((S->part[t] + S->part[64 + t]) + (S->part[128 + t] + S->part[192 + t]));
                float hv = softplusf(v);
#pragma unroll
                for (int d = 0; d < CL; d++)
                    st_async_f(mapa_u32(la_h2, d), mapa_u32(mb_h2, d), hv);
            }
            mbar_wait(mb_h2, par);
            // ---------- layer 3: 16 out x 512 k ----------
            {
                const float* wr = &S->w3t[o16*W3P + p16i*32];
                const float* hr = &S->h2[p16i*32];
                float4 a4 = make_float4(0.f,0.f,0.f,0.f);
#pragma unroll
                for (int kk = 0; kk < 8; kk++){
                    float4 w = *(const float4*)(wr + kk*4);
                    float4 x = *(const float4*)(hr + kk*4);
                    a4.x = fmaf(w.x, x.x, a4.x); a4.y = fmaf(w.y, x.y, a4.y);
                    a4.z = fmaf(w.z, x.z, a4.z); a4.w = fmaf(w.w, x.w, a4.w);
                }
                S->part[p16i*16 + o16] = (a4.x + a4.y) + (a4.z + a4.w);
            }
            __syncthreads();
            // post next-substep expects for h1/h2 BEFORE the z sends that
            // transitively enable the next phase's producers
            if (t == 0){ mbar_expect(mb_h1, 2048); mbar_expect(mb_h2, 2048); }
            __syncthreads();
            if (t < 16){
                float dv = S->b3s[t];
#pragma unroll
                for (int q = 0; q < 16; q++) dv += S->part[q*16 + t];
                float znew = S->z[cr*16 + t] + dtsub * dv;
#pragma unroll
                for (int d = 0; d < CL; d++)
                    st_async_f(mapa_u32(la_z, d), mapa_u32(mb_z, d), znew);
            }
            mbar_wait(mb_z, par);
            if (t == 0) mbar_expect(mb_z, 512);   // barrier now in next phase
            ph++;
        }
        // write interaction states matched to grid point j+1 (full z in smem)
        {
            int o = t & 15, ib = t >> 4, g = j + 1;
#pragma unroll
            for (int pass = 0; pass < 8; pass++){
                int i = pass*16 + ib;
                if (i < n && S->gsel[i] == g)
                    out[(size_t)b*OW + 2 + i*DIM + cr*16 + o] = S->z[cr*16 + o];
            }
        }
    }

    CLUSTER_SYNC_();

    // scores: rank 0 -> pos, rank 1 -> neg
    if (cr < 2){
        const int* pn = (cr == 0) ? pos : neg;
        float v = (t < DIM) ? S->z[t] * emb[(size_t)pn[b]*DIM + t] : 0.f;
#pragma unroll
        for (int o2 = 16; o2 > 0; o2 >>= 1) v += __shfl_xor_sync(0xffffffffu, v, o2);
        if ((t & 31) == 0) S->red[t >> 5] = v;
        __syncthreads();
        if (t == 0){
            float s = 0.f;
            for (int w = 0; w < TPB2/32; w++) s += S->red[w];
            out[(size_t)b*OW + cr] = s;
        }
    }
    __syncthreads();
    if (t == 0){ mbar_inval(mb_h1); mbar_inval(mb_h2); mbar_inval(mb_z); }
}

// ---------------- launch ----------------
extern "C" void kernel_launch(void* const* d_in, const int* in_sizes, int n_in,
                              void* d_out, int out_size)
{
    const float* emb   = (const float*)d_in[0];
    const float* mw1   = (const float*)d_in[1];
    const float* mb1   = (const float*)d_in[2];
    const float* mw2   = (const float*)d_in[3];
    const float* mb2   = (const float*)d_in[4];
    const float* usert = (const float*)d_in[5];
    const float* vw1   = (const float*)d_in[6];
    const float* vb1   = (const float*)d_in[7];
    const float* vw2   = (const float*)d_in[8];
    const float* vb2   = (const float*)d_in[9];
    const float* vw3   = (const float*)d_in[10];
    const float* vb3   = (const float*)d_in[11];
    const int*   u     = (const int*)d_in[12];
    const int*   hi    = (const int*)d_in[13];
    const float* ht    = (const float*)d_in[14];
    const int*   hl    = (const int*)d_in[15];
    const void*  p16   = d_in[16];
    const void*  p17   = d_in[17];
    const void*  p18   = d_in[18];
    float* out = (float*)d_out;

    static int smem_set = 0;
    if (!smem_set){
        cudaFuncSetAttribute(ode_cl_k, cudaFuncAttributeMaxDynamicSharedMemorySize,
                             (int)sizeof(OdeSmem));
        smem_set = 1;
    }

    dim3 ge(LQ, NB);
    enc_k<<<ge, DIM>>>(hi, emb, mw1, mb1, mw2, mb2, out);
    plan_k<<<NB, 128>>>(ht, hl, p16, p17, p18);
    ode_cl_k<<<NB*CL, TPB2, sizeof(OdeSmem)>>>(usert, u, vw1, vb1, vw2, vb2, vw3, vb3,
                                               emb, hl, p16, p17, p18, out);
}

// round 6
// speedup vs baseline: 1.3086x; 1.3086x over previous
#include <cuda_runtime.h>
#include <cstdint>
#include <math.h>

#define NB 4
#define LQ 128
#define DIM 128
#define HID 512
#define WWIN 5
#define MAXSEG 44
#define MAXINT 384
#define OW (2 + 2*LQ*DIM)   // 32770 floats per batch row

#define CL 8                // cluster size (CTAs per batch chain)
#define TPB2 256
#define MTP 516             // padded row stride (2064B, 16B-mult, conflict-free)

// ---------------- device scratch (no allocations allowed) ----------------
static __device__ float g_enc[NB*LQ*DIM];
static __device__ int   g_nInt[NB];
static __device__ float g_dt[NB*MAXINT];
static __device__ int   g_envSeg[NB*MAXINT];
static __device__ int   g_gsel[NB*LQ];
static __device__ int   g_segS[NB*MAXSEG];
static __device__ int   g_segE[NB*MAXSEG];
static __device__ float g_M[HID*HID];      // M = W1z · W3  (512x512)
static __device__ float g_zfin[NB*DIM];

__device__ __forceinline__ float softplusf(float x){
    return fmaxf(x, 0.f) + log1pf(expf(-fabsf(x)));
}

__device__ __forceinline__ bool is_index_arr(const void* p){
    int v = ((const int*)p)[0];
    return (v >= 0 && v < 1000000);
}

__device__ __forceinline__ uint32_t smem_u32(const void* p){
    return (uint32_t)__cvta_generic_to_shared(p);
}
__device__ __forceinline__ uint32_t mapa_u32(uint32_t la, uint32_t rank){
    uint32_t ra;
    asm volatile("mapa.shared::cluster.u32 %0, %1, %2;" : "=r"(ra) : "r"(la), "r"(rank));
    return ra;
}
__device__ __forceinline__ void st_async_f(uint32_t raddr, uint32_t rmbar, float v){
    asm volatile("st.async.shared::cluster.mbarrier::complete_tx::bytes.b32 [%0], %1, [%2];"
                 :: "r"(raddr), "r"(__float_as_uint(v)), "r"(rmbar) : "memory");
}
__device__ __forceinline__ void mbar_init(uint32_t mbar, uint32_t cnt){
    asm volatile("mbarrier.init.shared.b64 [%0], %1;" :: "r"(mbar), "r"(cnt) : "memory");
}
__device__ __forceinline__ void mbar_inval(uint32_t mbar){
    asm volatile("mbarrier.inval.shared.b64 [%0];" :: "r"(mbar) : "memory");
}
__device__ __forceinline__ void mbar_expect(uint32_t mbar, uint32_t bytes){
    asm volatile("mbarrier.arrive.expect_tx.shared.b64 _, [%0], %1;"
                 :: "r"(mbar), "r"(bytes) : "memory");
}
__device__ __forceinline__ void mbar_wait(uint32_t mbar, uint32_t parity){
    asm volatile("{\n\t"
        ".reg .pred P;\n\t"
        "LW%=:\n\t"
        "mbarrier.try_wait.parity.acquire.cluster.shared::cta.b64 P, [%0], %1, 0x989680;\n\t"
        "@P bra LD%=;\n\t"
        "bra LW%=;\n\t"
        "LD%=:\n\t"
        "}" :: "r"(mbar), "r"(parity) : "memory");
}

#define CLUSTER_SYNC_() do { \
    asm volatile("barrier.cluster.arrive.aligned;" ::: "memory"); \
    asm volatile("barrier.cluster.wait.aligned;" ::: "memory"); } while(0)

// ---------------- kernel 1: encoder (also writes traj_t) ----------------
__global__ void enc_k(const int* __restrict__ hi, const float* __restrict__ emb,
                      const float* __restrict__ w1, const float* __restrict__ b1,
                      const float* __restrict__ w2, const float* __restrict__ b2,
                      float* __restrict__ out)
{
    int l = blockIdx.x, b = blockIdx.y, t = threadIdx.x;
    __shared__ float e[DIM], h[DIM];
    int idx = hi[b*LQ + l];
    e[t] = emb[(size_t)idx*DIM + t];
    __syncthreads();
    float a = b1[t];
#pragma unroll 8
    for (int k = 0; k < DIM; k++) a = fmaf(e[k], w1[k*DIM + t], a);
    h[t] = fmaxf(a, 0.f);
    __syncthreads();
    float a2 = b2[t];
#pragma unroll 8
    for (int k = 0; k < DIM; k++) a2 = fmaf(h[k], w2[k*DIM + t], a2);
    g_enc[(b*LQ + l)*DIM + t] = a2;
    out[(size_t)b*OW + 2 + LQ*DIM + l*DIM + t] = a2;   // traj_t
}

// ---------------- kernel 1b: M = W1z * W3  (g_M[j*512+o]) ----------------
__global__ void mat_k(const float* __restrict__ vw1, const float* __restrict__ vw3)
{
    __shared__ float w3r[8*128];
    int t = threadIdx.x;                 // 128 threads
    int j0 = blockIdx.x * 8;             // 64 blocks x 8 rows
    for (int i = t; i < 8*128; i += 128) w3r[i] = vw3[j0*128 + i];
    __syncthreads();
    float acc[8][4];
#pragma unroll
    for (int jj = 0; jj < 8; jj++)
#pragma unroll
        for (int q = 0; q < 4; q++) acc[jj][q] = 0.f;
    for (int k = 0; k < 128; k++){
        float w1v[4];
#pragma unroll
        for (int q = 0; q < 4; q++) w1v[q] = vw1[k*HID + t + q*128];
#pragma unroll
        for (int jj = 0; jj < 8; jj++){
            float w3v = w3r[jj*128 + k];
#pragma unroll
            for (int q = 0; q < 4; q++) acc[jj][q] = fmaf(w3v, w1v[q], acc[jj][q]);
        }
    }
    for (int jj = 0; jj < 8; jj++)
#pragma unroll
        for (int q = 0; q < 4; q++)
            g_M[(size_t)(j0 + jj)*HID + t + q*128] = acc[jj][q];
}

// ---------------- block reduction over 128 threads ----------------
__device__ __forceinline__ float blkRed(float v, int op, float* sb){
#pragma unroll
    for (int o = 16; o > 0; o >>= 1){
        float v2 = __shfl_xor_sync(0xffffffffu, v, o);
        v = op ? fmaxf(v, v2) : (v + v2);
    }
    int w = threadIdx.x >> 5;
    if ((threadIdx.x & 31) == 0) sb[w] = v;
    __syncthreads();
    float r = op ? fmaxf(fmaxf(sb[0], sb[1]), fmaxf(sb[2], sb[3]))
                 : ((sb[0] + sb[1]) + (sb[2] + sb[3]));
    __syncthreads();
    return r;
}

// ---------------- kernel 2: APT partition + time-grid planning ----------------
__global__ void plan_k(const float* __restrict__ ht, const int* __restrict__ hl,
                       const void* __restrict__ p16, const void* __restrict__ p17,
                       const void* __restrict__ p18)
{
    int b = blockIdx.x, t = threadIdx.x;
    const float* pt;
    if (is_index_arr(p16)) pt = (const float*)p18;   // order: pos,neg,pt
    else                   pt = (const float*)p16;   // order: pt,pos,neg

    __shared__ double times[LQ];
    __shared__ double bounds[MAXSEG + 2];
    __shared__ int starts[MAXSEG + 1];
    __shared__ float sb[4];
    __shared__ int sj, snb, sns, sm_m, scum;
    __shared__ double ts[LQ + 8];

    int n = hl[b]; if (n > LQ) n = LQ;
    if (t < n) times[t] = (double)ht[b*LQ + t];
    if (t == 0){ sj = 0; snb = 1; sns = 1; bounds[0] = (double)ht[b*LQ]; starts[0] = 0; scum = 0; }
    __syncthreads();

    if (n >= 2*WWIN){
        for (;;){
            __syncthreads();
            int j = sj;
            if (j > n - 2*WWIN) break;
            float sL = 0.f, sR = 0.f;
            const float* base = &g_enc[(b*LQ + j)*DIM + t];
#pragma unroll
            for (int r = 0; r < WWIN; r++){ sL += base[r*DIM]; sR += base[(WWIN + r)*DIM]; }
            sL /= (float)WWIN; sR /= (float)WWIN;
            float mL = blkRed(sL, 1, sb);
            float mR = blkRed(sR, 1, sb);
            float eL = expf(sL - mL), eR = expf(sR - mR);
            float suL = blkRed(eL, 0, sb);
            float suR = blkRed(eR, 0, sb);
            float p = eL/suL + 1e-8f;
            float q = eR/suR + 1e-8f;
            float ps = blkRed(p, 0, sb);
            float qs = blkRed(q, 0, sb);
            p /= ps; q /= qs;
            float m  = 0.5f*(p + q);
            float c  = 0.5f*p*logf(p/m) + 0.5f*q*logf(q/m);
            float jsd = blkRed(c, 0, sb);
            if (t == 0){
                if (jsd > 0.5f){
                    bounds[snb] = 0.5*(times[j + WWIN - 1] + times[j + WWIN]);
                    snb++;
                    starts[sns] = j + WWIN; sns++;
                    sj = j + WWIN;
                } else sj = j + 1;
            }
        }
    }
    __syncthreads();
    if (t == 0){
        if (times[n-1] > bounds[snb-1]) { bounds[snb] = times[n-1]; snb++; }
    }
    __syncthreads();

    int nseg = sns, nb2 = snb;
    for (int si = 0; si < nseg; si++){
        int s = starts[si];
        int e = (si + 1 < nseg) ? starts[si+1] - 1 : n - 1;
        if (t == 0){
            g_segS[b*MAXSEG + si] = s; g_segE[b*MAXSEG + si] = e;
            double t0 = bounds[si];
            double t1 = (si + 1 < nb2) ? bounds[si+1] : bounds[nb2-1];
            int m = 0; ts[m++] = t0;
            for (int i = s; i <= e; i++){
                double d = times[i];
                if (d >= t0 && d <= t1 && d != ts[m-1]) ts[m++] = d;
            }
            if (t1 != ts[m-1]) ts[m++] = t1;
            for (int k = 1; k < m; k++)
                if (ts[k] - ts[k-1] < 1e-6) ts[k] = ts[k-1] + 1e-6;
            for (int k = 0; k < m - 1; k++){
                g_dt[b*MAXINT + scum + k] = (float)(ts[k+1] - ts[k]);
                g_envSeg[b*MAXINT + scum + k] = si;
            }
            sm_m = m;
        }
        __syncthreads();
        int m = sm_m, cum = scum;
        for (int i = s + t; i <= e; i += blockDim.x){
            double ti = times[i];
            int best = 0; double bd = fabs(ts[0] - ti);
            for (int k = 1; k < m; k++){
                double dd = fabs(ts[k] - ti);
                if (dd < bd){ bd = dd; best = k; }
            }
            g_gsel[b*LQ + i] = cum + best;
        }
        __syncthreads();
        if (t == 0) scum += m - 1;
        __syncthreads();
    }
    if (t == 0){
        int cum = scum;
        double lb = bounds[nb2-1];
        double ptb = (double)pt[b];
        if (ptb > lb + 1e-6){
            double t1 = ptb;
            if (t1 - lb < 1e-6) t1 = lb + 1e-6;
            g_dt[b*MAXINT + cum] = (float)(t1 - lb);
            g_envSeg[b*MAXINT + cum] = nseg - 1;
            cum++;
        }
        g_nInt[b] = cum;
    }
}

// ---------------- kernel 3: clustered Euler ODE, a = W1z·z recurrence ----------------
// 32B header keeps every array 16B-aligned; all sizes are 16B multiples.
struct __align__(16) OdeSmem {
    unsigned long long mb[4];   // 0: h1, 1: h2, rest pad
    float mt[64*MTP];           // M column-slice transposed [o][j] (132KB); staging area at init
    float w3s[16*MTP];          // W3 column-slice [i][j] (33KB)
    float cenvAll[MAXSEG*64];
    float env[DIM];             // z0 staging
    float h1[HID];
    float h2[HID];
    float part[4*64];
    float part2[16*16];
    float zs[16];
    float b2s[64];
    float c3s[64];
    float b3s[16];
    float aval[64];
    float dtv[MAXINT];
    int   eseg[MAXINT];
    int   segS[MAXSEG];
    int   segE[MAXSEG];
    int   gsel[LQ];
};

extern __shared__ __align__(16) char ode_raw[];

__global__ void __launch_bounds__(TPB2, 1) __cluster_dims__(CL, 1, 1)
ode_cl_k(const float* __restrict__ usert, const int* __restrict__ u,
         const float* __restrict__ vw1, const float* __restrict__ vb1,
         const float* __restrict__ vw2, const float* __restrict__ vb2,
         const float* __restrict__ vw3, const float* __restrict__ vb3,
         const int* __restrict__ hl,
         float* __restrict__ out)
{
    OdeSmem* S = (OdeSmem*)ode_raw;
    int t = threadIdx.x;
    uint32_t cr; asm("mov.u32 %0, %%cluster_ctarank;" : "=r"(cr));
    int b = blockIdx.x / CL;

    const int o64 = t & 63, p4 = t >> 6;     // 64 outs x 4 k-parts
    const int o16 = t & 15, p16i = t >> 4;   // 16 outs x 16 k-parts

    // ---- layer-2 weight slice into registers ----
    float w2r[128];
    {
        const float* base = &vw2[(size_t)(p4*128)*HID + cr*64 + o64];
#pragma unroll
        for (int kk = 0; kk < 128; kk++) w2r[kk] = base[(size_t)kk*HID];
    }

    // ---- stage W1 z-half & env-half slices in mt space (freed before mt load) ----
    float* wz   = S->mt;              // [128][64]
    float* wenv = S->mt + 8192;       // [128][64]
    for (int idx = t; idx < 8192; idx += TPB2){
        int k = idx >> 6, o = idx & 63;
        wz[k*64 + o]   = vw1[(size_t)k*HID + cr*64 + o];
        wenv[k*64 + o] = vw1[(size_t)(DIM + k)*HID + cr*64 + o];
    }
    if (t < DIM) S->env[t] = usert[(size_t)u[b]*DIM + t];   // z0
    for (int i = t; i < MAXINT; i += TPB2){
        S->dtv[i]  = g_dt[b*MAXINT + i];
        S->eseg[i] = g_envSeg[b*MAXINT + i];
    }
    for (int i = t; i < MAXSEG; i += TPB2){
        S->segS[i] = g_segS[b*MAXSEG + i];
        S->segE[i] = g_segE[b*MAXSEG + i];
    }
    for (int i = t; i < LQ; i += TPB2) S->gsel[i] = g_gsel[b*LQ + i];
    if (t < 64) S->b2s[t] = vb2[cr*64 + t];
    if (t < 16) S->b3s[t] = vb3[cr*16 + t];
    __syncthreads();

    // ---- a0 = W1z·z0 and c3 = W1z·b3 (partials over 4 k-groups) ----
    {
        float az = 0.f, ac = 0.f;
        const float* wp = &wz[(p4*32)*64 + o64];
        const float* zp = &S->env[p4*32];
#pragma unroll 8
        for (int kk = 0; kk < 32; kk++){
            float wv = wp[kk*64];
            az = fmaf(zp[kk], wv, az);
            ac = fmaf(vb3[p4*32 + kk], wv, ac);
        }
        S->part [p4*64 + o64] = az;
        S->part2[p4*64 + o64] = ac;
    }
    __syncthreads();
    if (t < 64){
        S->aval[t] = (S->part[t] + S->part[64+t]) + (S->part[128+t] + S->part[192+t]);
        S->c3s[t]  = (S->part2[t] + S->part2[64+t]) + (S->part2[128+t] + S->part2[192+t]);
    }
    __syncthreads();

    int nInt = g_nInt[b];
    int nseg = S->eseg[nInt - 1] + 1;
    int n = hl[b]; if (n > LQ) n = LQ;

    // ---- per-segment cenv = vb1 + Wenv·mean(enc[s..e]) ----
    for (int si = 0; si < nseg; si++){
        int s = S->segS[si], e = S->segE[si];
        if (t < DIM){
            float a = 0.f;
            for (int r2 = s; r2 <= e; r2++) a += g_enc[(b*LQ + r2)*DIM + t];
            S->h1[t] = a / (float)(e - s + 1);
        }
        __syncthreads();
        {
            float a = 0.f;
            const float* wp = &wenv[(p4*32)*64 + o64];
            const float* ep = &S->h1[p4*32];
#pragma unroll 8
            for (int kk = 0; kk < 32; kk++) a = fmaf(ep[kk], wp[kk*64], a);
            S->part[p4*64 + o64] = a;
        }
        __syncthreads();
        if (t < 64)
            S->cenvAll[si*64 + t] = vb1[cr*64 + t] +
                ((S->part[t] + S->part[64+t]) + (S->part[128+t] + S->part[192+t]));
        __syncthreads();
    }

    // ---- load M slice (overwrites staging) + W3 slice + z slice ----
    for (int idx = t; idx < 64*HID; idx += TPB2){
        int jj = idx >> 6, o = idx & 63;
        S->mt[o*MTP + jj] = g_M[(size_t)jj*HID + cr*64 + o];
    }
    for (int idx = t; idx < 16*HID; idx += TPB2){
        int jj = idx >> 4, o = idx & 15;
        S->w3s[o*MTP + jj] = vw3[jj*DIM + cr*16 + o];
    }
    if (t < 16) S->zs[t] = S->env[cr*16 + t];

    uint32_t mb_h1 = smem_u32(&S->mb[0]);
    uint32_t mb_h2 = smem_u32(&S->mb[1]);
    if (t == 0){ mbar_init(mb_h1, 1); mbar_init(mb_h2, 1); }
    __syncthreads();
    if (t == 0){ mbar_expect(mb_h1, 2048); mbar_expect(mb_h2, 2048); }
    __syncthreads();
    CLUSTER_SYNC_();

    // precomputed remote addresses (each thread sends its value to ranks p4 and p4+4)
    uint32_t la_h1 = smem_u32(&S->h1[cr*64 + o64]);
    uint32_t la_h2 = smem_u32(&S->h2[cr*64 + o64]);
    uint32_t ra_h1_a = mapa_u32(la_h1, p4), ra_h1_b = mapa_u32(la_h1, p4 + 4);
    uint32_t rb_h1_a = mapa_u32(mb_h1, p4), rb_h1_b = mapa_u32(mb_h1, p4 + 4);
    uint32_t ra_h2_a = mapa_u32(la_h2, p4), ra_h2_b = mapa_u32(la_h2, p4 + 4);
    uint32_t rb_h2_a = mapa_u32(mb_h2, p4), rb_h2_b = mapa_u32(mb_h2, p4 + 4);

    // grid-0 state writes (z0 slice)
    {
#pragma unroll
        for (int pass = 0; pass < 8; pass++){
            int i = pass*16 + p16i;
            if (i < n && S->gsel[i] == 0)
                out[(size_t)b*OW + 2 + (size_t)i*DIM + cr*16 + o16] = S->zs[o16];
        }
    }

    int ph = 0;
    for (int j = 0; j < nInt; j++){
        const float* cenv = &S->cenvAll[S->eseg[j]*64];
        float dtsub = 0.5f * S->dtv[j];   // dt / NSUB, NSUB=2
        for (int sub = 0; sub < 2; sub++){
            uint32_t par = (uint32_t)(ph & 1);
            // ---- h1 = softplus(cenv + a): no GEMV, broadcast slice ----
            {
                float hv = softplusf(cenv[o64] + S->aval[o64]);
                st_async_f(ra_h1_a, rb_h1_a, hv);
                st_async_f(ra_h1_b, rb_h1_b, hv);
            }
            mbar_wait(mb_h1, par);
            if (t == 0) mbar_expect(mb_h1, 2048);
            // ---- layer 2: 64 out x 512 k, weights in registers ----
            {
                const float4* hr = (const float4*)&S->h1[p4*128];
                float4 a4 = make_float4(0.f,0.f,0.f,0.f);
#pragma unroll
                for (int kk = 0; kk < 32; kk++){
                    float4 h = hr[kk];
                    a4.x = fmaf(h.x, w2r[kk*4+0], a4.x);
                    a4.y = fmaf(h.y, w2r[kk*4+1], a4.y);
                    a4.z = fmaf(h.z, w2r[kk*4+2], a4.z);
                    a4.w = fmaf(h.w, w2r[kk*4+3], a4.w);
                }
                S->part[p4*64 + o64] = (a4.x + a4.y) + (a4.z + a4.w);
            }
            __syncthreads();
            {
                float v = S->b2s[o64] +
                    ((S->part[o64] + S->part[64+o64]) + (S->part[128+o64] + S->part[192+o64]));
                float hv = softplusf(v);
                st_async_f(ra_h2_a, rb_h2_a, hv);
                st_async_f(ra_h2_b, rb_h2_b, hv);
            }
            mbar_wait(mb_h2, par);
            if (t == 0) mbar_expect(mb_h2, 2048);
            // ---- a' = a + dt(c3 + M·h2) partials, and z-slice partials ----
            {
                const float* wr = &S->mt[o64*MTP + p4*128];
                const float4* hr = (const float4*)&S->h2[p4*128];
                float4 a4 = make_float4(0.f,0.f,0.f,0.f);
#pragma unroll
                for (int kk = 0; kk < 32; kk++){
                    float4 w = *(const float4*)(wr + kk*4);
                    float4 h = hr[kk];
                    a4.x = fmaf(w.x, h.x, a4.x); a4.y = fmaf(w.y, h.y, a4.y);
                    a4.z = fmaf(w.z, h.z, a4.z); a4.w = fmaf(w.w, h.w, a4.w);
                }
                S->part[p4*64 + o64] = (a4.x + a4.y) + (a4.z + a4.w);
            }
            {
                const float* wr = &S->w3s[o16*MTP + p16i*32];
                const float* hr = &S->h2[p16i*32];
                float4 a4 = make_float4(0.f,0.f,0.f,0.f);
#pragma unroll
                for (int kk = 0; kk < 8; kk++){
                    float4 w = *(const float4*)(wr + kk*4);
                    float4 x = *(const float4*)(hr + kk*4);
                    a4.x = fmaf(w.x, x.x, a4.x); a4.y = fmaf(w.y, x.y, a4.y);
                    a4.z = fmaf(w.z, x.z, a4.z); a4.w = fmaf(w.w, x.w, a4.w);
                }
                S->part2[p16i*16 + o16] = (a4.x + a4.y) + (a4.z + a4.w);
            }
            __syncthreads();
            if (t < 64){
                float tot = (S->part[t] + S->part[64+t]) + (S->part[128+t] + S->part[192+t]);
                S->aval[t] += dtsub * (S->c3s[t] + tot);
            }
            if (t >= 64 && t < 80){
                int i = t - 64;
                float dv = S->b3s[i];
#pragma unroll
                for (int q = 0; q < 16; q++) dv += S->part2[q*16 + i];
                S->zs[i] += dtsub * dv;
            }
            __syncthreads();
            ph++;
        }
        // write interaction states (local 16-component slice)
        {
            int g = j + 1;
#pragma unroll
            for (int pass = 0; pass < 8; pass++){
                int i = pass*16 + p16i;
                if (i < n && S->gsel[i] == g)
                    out[(size_t)b*OW + 2 + (size_t)i*DIM + cr*16 + o16] = S->zs[o16];
            }
        }
    }

    if (t < 16) g_zfin[b*DIM + cr*16 + t] = S->zs[t];
    CLUSTER_SYNC_();
    if (t == 0){ mbar_inval(mb_h1); mbar_inval(mb_h2); }
}

// ---------------- kernel 4: scores ----------------
__global__ void score_k(const float* __restrict__ emb,
                        const void* __restrict__ p16, const void* __restrict__ p17,
                        const void* __restrict__ p18, float* __restrict__ out)
{
    int b = blockIdx.x, t = threadIdx.x;   // 128 threads
    const int *pos, *neg;
    if (is_index_arr(p16)) { pos = (const int*)p16; neg = (const int*)p17; }
    else                   { pos = (const int*)p17; neg = (const int*)p18; }
    __shared__ float sb[8];
    float z = g_zfin[b*DIM + t];
    for (int which = 0; which < 2; which++){
        const int* pn = which ? neg : pos;
        float v = z * emb[(size_t)pn[b]*DIM + t];
#pragma unroll
        for (int o = 16; o > 0; o >>= 1) v += __shfl_xor_sync(0xffffffffu, v, o);
        if ((t & 31) == 0) sb[t >> 5] = v;
        __syncthreads();
        if (t == 0) out[(size_t)b*OW + which] = (sb[0] + sb[1]) + (sb[2] + sb[3]);
        __syncthreads();
    }
}

// ---------------- launch ----------------
extern "C" void kernel_launch(void* const* d_in, const int* in_sizes, int n_in,
                              void* d_out, int out_size)
{
    const float* emb   = (const float*)d_in[0];
    const float* mw1   = (const float*)d_in[1];
    const float* mb1   = (const float*)d_in[2];
    const float* mw2   = (const float*)d_in[3];
    const float* mb2   = (const float*)d_in[4];
    const float* usert = (const float*)d_in[5];
    const float* vw1   = (const float*)d_in[6];
    const float* vb1   = (const float*)d_in[7];
    const float* vw2   = (const float*)d_in[8];
    const float* vb2   = (const float*)d_in[9];
    const float* vw3   = (const float*)d_in[10];
    const float* vb3   = (const float*)d_in[11];
    const int*   u     = (const int*)d_in[12];
    const int*   hi    = (const int*)d_in[13];
    const float* ht    = (const float*)d_in[14];
    const int*   hl    = (const int*)d_in[15];
    const void*  p16   = d_in[16];
    const void*  p17   = d_in[17];
    const void*  p18   = d_in[18];
    float* out = (float*)d_out;

    static int smem_set = 0;
    if (!smem_set){
        cudaFuncSetAttribute(ode_cl_k, cudaFuncAttributeMaxDynamicSharedMemorySize,
                             (int)sizeof(OdeSmem));
        smem_set = 1;
    }

    dim3 ge(LQ, NB);
    enc_k<<<ge, DIM>>>(hi, emb, mw1, mb1, mw2, mb2, out);
    mat_k<<<64, 128>>>(vw1, vw3);
    plan_k<<<NB, 128>>>(ht, hl, p16, p17, p18);
    ode_cl_k<<<NB*CL, TPB2, sizeof(OdeSmem)>>>(usert, u, vw1, vb1, vw2, vb2, vw3, vb3,
                                               hl, out);
    score_k<<<NB, 128>>>(emb, p16, p17, p18, out);
}